// round 1
// baseline (speedup 1.0000x reference)
#include <cuda_runtime.h>
#include <cuda_bf16.h>

#define T_DIM 1024
#define F_DIM 128
#define UNROLL 8
#define EPS_F 1e-5f

// One block per (b, c) row. 128 threads, thread = f index.
// Each thread walks t serially keeping running sum / sumsq.
// Loads/stores are fully coalesced (adjacent threads -> adjacent f).
__global__ __launch_bounds__(128, 8)
void cumulative_groupnorm_kernel(const float* __restrict__ x,
                                 const float* __restrict__ weight,
                                 const float* __restrict__ bias,
                                 float* __restrict__ out,
                                 int C)
{
    __shared__ float s_inv[T_DIM];   // 1/(t+1) LUT, broadcast reads
    const int f  = threadIdx.x;
    const int bc = blockIdx.x;

    // Fill reciprocal LUT (8 MUFU.RCP per thread, once per block)
    #pragma unroll
    for (int i = 0; i < T_DIM / F_DIM; i++) {
        int idx = f + i * F_DIM;
        s_inv[idx] = 1.0f / (float)(idx + 1);
    }
    __syncthreads();

    const int c = bc % C;
    const float w  = weight[c];
    const float bb = bias[c];

    const size_t base = (size_t)bc * T_DIM * F_DIM + f;
    const float* __restrict__ xp = x + base;
    float* __restrict__ op = out + base;

    float sum = 0.0f, sumsq = 0.0f;

    #pragma unroll 1
    for (int t = 0; t < T_DIM; t += UNROLL) {
        // Front-batched independent loads -> MLP = UNROLL
        float v[UNROLL];
        #pragma unroll
        for (int j = 0; j < UNROLL; j++)
            v[j] = xp[(size_t)(t + j) * F_DIM];

        float o[UNROLL];
        #pragma unroll
        for (int j = 0; j < UNROLL; j++) {
            const float val = v[j];
            sum   += val;
            sumsq  = fmaf(val, val, sumsq);
            const float inv  = s_inv[t + j];
            const float mean = sum   * inv;
            const float msq  = sumsq * inv;
            const float var  = fmaf(-mean, mean, msq);
            const float r    = rsqrtf(var + EPS_F);
            o[j] = fmaf((val - mean) * r, w, bb);
        }

        #pragma unroll
        for (int j = 0; j < UNROLL; j++)
            op[(size_t)(t + j) * F_DIM] = o[j];
    }
}

extern "C" void kernel_launch(void* const* d_in, const int* in_sizes, int n_in,
                              void* d_out, int out_size)
{
    const float* x      = (const float*)d_in[0];
    const float* weight = (const float*)d_in[1];
    const float* bias   = (const float*)d_in[2];
    float* out          = (float*)d_out;

    const int C    = in_sizes[1];                       // 256
    const int n_bc = in_sizes[0] / (T_DIM * F_DIM);     // B*C = 1024

    cumulative_groupnorm_kernel<<<n_bc, F_DIM>>>(x, weight, bias, out, C);
}